// round 6
// baseline (speedup 1.0000x reference)
#include <cuda_runtime.h>
#include <cuda_bf16.h>
#include <cstdint>

// Problem constants
#define Bq   4
#define Nq   2048
#define FIN  128
#define Hq   4
#define Dq   64
#define ALPHA 0.2f
#define NSPLIT 8               // j-dimension splits of k_attn
#define JCHUNK (Nq / NSPLIT)   // 256
#define TJ   128               // j subtile inside a chunk

// Scratch (allocation-free rule: __device__ globals)
__device__ float g_h[Bq * Hq * Nq * Dq];                  // [bh][n][d] (8 MB)
__device__ float g_num[NSPLIT * Bq * Hq * Nq * Dq];       // partial numerators (67 MB)
__device__ float g_den[NSPLIT * Bq * Hq * Nq];            // partial denominators
__device__ float g_ei[Bq * Hq * Nq];
__device__ float g_ej[Bq * Hq * Nq];

// ---- packed f32x2 helpers (sm_103a) ---------------------------------------
__device__ __forceinline__ unsigned long long pk2(float lo, float hi) {
    unsigned long long r;
    asm("mov.b64 %0, {%1,%2};" : "=l"(r) : "f"(lo), "f"(hi));
    return r;
}
__device__ __forceinline__ void fma2(unsigned long long& d,
                                     unsigned long long a,
                                     unsigned long long b) {
    asm("fma.rn.f32x2 %0, %1, %2, %0;" : "+l"(d) : "l"(a), "l"(b));
}
__device__ __forceinline__ float2 upk(unsigned long long v) {
    float2 f;
    asm("mov.b64 {%0,%1}, %2;" : "=f"(f.x), "=f"(f.y) : "l"(v));
    return f;
}

// ---------------------------------------------------------------------------
// Kernel 1: h = x @ W -> g_h[b][head][n][d]
// ---------------------------------------------------------------------------
__global__ __launch_bounds__(256) void k_gemm(const float* __restrict__ x,
                                              const float* __restrict__ W) {
    __shared__ float Ws[32 * 256];
    __shared__ float xs[32 * 33];

    const int tid  = threadIdx.x;
    const int row0 = blockIdx.x * 32;
    const int ty   = tid >> 4;
    const int tx   = tid & 15;

    unsigned long long acc2[2][8];
#pragma unroll
    for (int r = 0; r < 2; r++)
#pragma unroll
        for (int c = 0; c < 8; c++) acc2[r][c] = 0ull;

    for (int kc = 0; kc < FIN; kc += 32) {
        __syncthreads();
        const float4* W4 = (const float4*)(W + kc * 256);
#pragma unroll
        for (int t = 0; t < 8; t++) {
            int idx = tid + 256 * t;
            ((float4*)Ws)[idx] = W4[idx];
        }
        {
            int r  = tid >> 3;
            int kq = tid & 7;
            float4 v = *(const float4*)(x + (size_t)(row0 + r) * FIN + kc + kq * 4);
            float* dst = &xs[r * 33 + kq * 4];
            dst[0] = v.x; dst[1] = v.y; dst[2] = v.z; dst[3] = v.w;
        }
        __syncthreads();
#pragma unroll
        for (int k = 0; k < 32; k++) {
            float x0 = xs[(ty * 2 + 0) * 33 + k];
            float x1 = xs[(ty * 2 + 1) * 33 + k];
            unsigned long long xp0 = pk2(x0, x0);
            unsigned long long xp1 = pk2(x1, x1);
#pragma unroll
            for (int c = 0; c < 8; c++) {
                unsigned long long wv =
                    *(const unsigned long long*)&Ws[k * 256 + tx * 2 + c * 32];
                fma2(acc2[0][c], xp0, wv);
                fma2(acc2[1][c], xp1, wv);
            }
        }
    }

#pragma unroll
    for (int r = 0; r < 2; r++) {
        int g = row0 + ty * 2 + r;
        int b = g / Nq;
        int n = g % Nq;
#pragma unroll
        for (int c = 0; c < 8; c++) {
            int o    = tx * 2 + c * 32;
            int head = o >> 6;
            int d    = o & 63;
            float2 v = upk(acc2[r][c]);
            *(float2*)&g_h[(((size_t)b * Hq + head) * Nq + n) * Dq + d] = v;
        }
    }
}

// ---------------------------------------------------------------------------
// Kernel 2: ei/ej per (b,head,n). One warp per row.
// ---------------------------------------------------------------------------
__global__ __launch_bounds__(256) void k_ev(const float* __restrict__ a) {
    int task = blockIdx.x * 8 + (threadIdx.x >> 5);
    int lane = threadIdx.x & 31;
    const float* hr = g_h + (size_t)task * Dq;
    float v0 = hr[lane], v1 = hr[lane + 32];
    float e1 = v0 * a[lane]      + v1 * a[lane + 32];
    float e2 = v0 * a[64 + lane] + v1 * a[96 + lane];
#pragma unroll
    for (int off = 16; off > 0; off >>= 1) {
        e1 += __shfl_down_sync(0xffffffffu, e1, off);
        e2 += __shfl_down_sync(0xffffffffu, e2, off);
    }
    if (lane == 0) {
        g_ei[task] = e1;
        g_ej[task] = e2;
    }
}

// ---------------------------------------------------------------------------
// Kernel 3: attention partials, TJ=128 subtiles, 4 barriers per CTA total.
// Dynamic smem ~102 KB -> 2 CTAs/SM. Grid 512 = (s, it, head, b).
// smem layout (floats): ei[128] | ej[128] | V[128*64] | p[128*132] | dn[128]
// ---------------------------------------------------------------------------
#define SM_EI   0
#define SM_EJ   128
#define SM_V    256
#define SM_P    (256 + 128 * 64)
#define SM_DN   (SM_P + 128 * 132)
#define SM_FLOATS (SM_DN + 128)

__global__ __launch_bounds__(256) void k_attn(const int* __restrict__ adj) {
    extern __shared__ float sm[];
    float* ei_s = sm + SM_EI;
    float* ej_s = sm + SM_EJ;
    float* V_s  = sm + SM_V;
    float* p_s  = sm + SM_P;
    float* dn_s = sm + SM_DN;

    const int tid  = threadIdx.x;
    const int s    = blockIdx.x & (NSPLIT - 1);
    const int bt   = blockIdx.x >> 3;
    const int it   = bt & 15;
    const int head = (bt >> 4) & 3;
    const int b    = bt >> 6;
    const int i0   = it * 128;
    const int bh   = b * Hq + head;
    const int jb   = s * JCHUNK;

    const float* Vg      = g_h + (size_t)bh * Nq * Dq;
    const int*   adj_row = adj + ((size_t)b * Nq + i0) * Nq + jb;

    if (tid < 128) ei_s[tid] = g_ei[bh * Nq + i0 + tid];

    const int ty = tid >> 3;
    const int tx = tid & 7;

    unsigned long long acc2[4][4];
#pragma unroll
    for (int r = 0; r < 4; r++)
#pragma unroll
        for (int c = 0; c < 4; c++) acc2[r][c] = 0ull;
    float den[4] = {0.f, 0.f, 0.f, 0.f};

#pragma unroll
    for (int jt = 0; jt < JCHUNK / TJ; jt++) {
        const int jbase = jb + jt * TJ;
        __syncthreads();   // protect V_s/p_s reuse from previous subtile

        // V subtile: 128 x 64 floats = 2048 float4, 8 per thread (batched)
        {
            const float4* Vt = (const float4*)(Vg + (size_t)jbase * Dq);
            float4* Vd = (float4*)V_s;
#pragma unroll
            for (int t = 0; t < 8; t++) Vd[tid + 256 * t] = Vt[tid + 256 * t];
        }
        if (tid < 128) ej_s[tid] = g_ej[bh * Nq + jbase + tid];
        __syncthreads();

        // p subtile: 128 x 128, int4 adj loads (16 per thread, high MLP)
#pragma unroll
        for (int t = 0; t < 16; t++) {
            int idx4 = tid + 256 * t;          // 0..4095
            int i    = idx4 >> 5;              // 0..127
            int j4   = (idx4 & 31) * 4;        // 0,4,...,124
            int4 av = *(const int4*)&adj_row[(size_t)i * Nq + jt * TJ + j4];
            float eb = ei_s[i];
            float e0 = eb + ej_s[j4 + 0];
            float e1 = eb + ej_s[j4 + 1];
            float e2 = eb + ej_s[j4 + 2];
            float e3 = eb + ej_s[j4 + 3];
            e0 = fmaxf(e0, ALPHA * e0);
            e1 = fmaxf(e1, ALPHA * e1);
            e2 = fmaxf(e2, ALPHA * e2);
            e3 = fmaxf(e3, ALPHA * e3);
            float4 p;
            p.x = av.x ? __expf(e0) : 0.f;
            p.y = av.y ? __expf(e1) : 0.f;
            p.z = av.z ? __expf(e2) : 0.f;
            p.w = av.w ? __expf(e3) : 0.f;
            *(float4*)&p_s[i * 132 + j4] = p;
        }
        __syncthreads();

        // PV: 128 j iterations, no barriers
#pragma unroll 4
        for (int j = 0; j < TJ; j++) {
            ulonglong2 v0 = *(const ulonglong2*)&V_s[j * 64 + tx * 8];
            ulonglong2 v1 = *(const ulonglong2*)&V_s[j * 64 + tx * 8 + 4];
            float p0 = p_s[(ty * 4 + 0) * 132 + j];
            float p1 = p_s[(ty * 4 + 1) * 132 + j];
            float p2 = p_s[(ty * 4 + 2) * 132 + j];
            float p3 = p_s[(ty * 4 + 3) * 132 + j];
            if (tx == 0) { den[0] += p0; den[1] += p1; den[2] += p2; den[3] += p3; }
            unsigned long long pp0 = pk2(p0, p0);
            unsigned long long pp1 = pk2(p1, p1);
            unsigned long long pp2 = pk2(p2, p2);
            unsigned long long pp3 = pk2(p3, p3);
            fma2(acc2[0][0], pp0, v0.x); fma2(acc2[0][1], pp0, v0.y);
            fma2(acc2[0][2], pp0, v1.x); fma2(acc2[0][3], pp0, v1.y);
            fma2(acc2[1][0], pp1, v0.x); fma2(acc2[1][1], pp1, v0.y);
            fma2(acc2[1][2], pp1, v1.x); fma2(acc2[1][3], pp1, v1.y);
            fma2(acc2[2][0], pp2, v0.x); fma2(acc2[2][1], pp2, v0.y);
            fma2(acc2[2][2], pp2, v1.x); fma2(acc2[2][3], pp2, v1.y);
            fma2(acc2[3][0], pp3, v0.x); fma2(acc2[3][1], pp3, v0.y);
            fma2(acc2[3][2], pp3, v1.x); fma2(acc2[3][3], pp3, v1.y);
        }
    }

    __syncthreads();
    if (tx == 0) {
#pragma unroll
        for (int r = 0; r < 4; r++) dn_s[ty * 4 + r] = den[r];
    }
    __syncthreads();

    float* ng = g_num + (((size_t)s * Bq * Hq + bh) * Nq + i0) * Dq;
    if (tid < 128)
        g_den[((size_t)s * Bq * Hq + bh) * Nq + i0 + tid] = dn_s[tid];
#pragma unroll
    for (int r = 0; r < 4; r++) {
        float2 e0 = upk(acc2[r][0]);
        float2 e1 = upk(acc2[r][1]);
        float2 e2 = upk(acc2[r][2]);
        float2 e3 = upk(acc2[r][3]);
        float4 w0, w1;
        w0.x = e0.x; w0.y = e0.y; w0.z = e1.x; w0.w = e1.y;
        w1.x = e2.x; w1.y = e2.y; w1.z = e3.x; w1.w = e3.y;
        *(float4*)&ng[(ty * 4 + r) * Dq + tx * 8]     = w0;
        *(float4*)&ng[(ty * 4 + r) * Dq + tx * 8 + 4] = w1;
    }
}

// ---------------------------------------------------------------------------
// Kernel 4: combine partials over splits, divide, mean over heads.
// ---------------------------------------------------------------------------
__global__ __launch_bounds__(256) void k_comb(float* __restrict__ out) {
    int idx = blockIdx.x * 256 + threadIdx.x;
    if (idx >= Bq * Nq * Dq) return;
    int d = idx & 63;
    int n = (idx >> 6) & (Nq - 1);
    int b = idx >> 17;
    float res = 0.f;
#pragma unroll
    for (int h = 0; h < Hq; h++) {
        int bh = b * Hq + h;
        float num = 0.f, den = 0.f;
#pragma unroll
        for (int s = 0; s < NSPLIT; s++) {
            num += g_num[(((size_t)s * Bq * Hq + bh) * Nq + n) * Dq + d];
            den += g_den[((size_t)s * Bq * Hq + bh) * Nq + n];
        }
        res += num / den;
    }
    out[idx] = 0.25f * res;
}

// ---------------------------------------------------------------------------
extern "C" void kernel_launch(void* const* d_in, const int* in_sizes, int n_in,
                              void* d_out, int out_size) {
    const float* x   = (const float*)d_in[0];
    const int*   adj = (const int*)  d_in[1];
    const float* W   = (const float*)d_in[2];
    const float* a   = (const float*)d_in[3];
    float*       out = (float*)d_out;

    const int smem_bytes = SM_FLOATS * sizeof(float);   // ~102 KB
    cudaFuncSetAttribute(k_attn, cudaFuncAttributeMaxDynamicSharedMemorySize,
                         smem_bytes);

    k_gemm<<<(Bq * Nq) / 32, 256>>>(x, W);
    k_ev  <<<(Bq * Hq * Nq) / 8, 256>>>(a);
    k_attn<<<Bq * Hq * (Nq / 128) * NSPLIT, 256, smem_bytes>>>(adj);
    k_comb<<<(Bq * Nq * Dq + 255) / 256, 256>>>(out);
}

// round 10
// speedup vs baseline: 1.6361x; 1.6361x over previous
#include <cuda_runtime.h>
#include <cuda_bf16.h>
#include <cstdint>

// Problem constants
#define Bq   4
#define Nq   2048
#define FIN  128
#define Hq   4
#define Dq   64
#define ALPHA 0.2f

// Scratch
__device__ float g_h[Bq * Hq * Nq * Dq];    // [bh][n][d] (8 MB)
__device__ float g_o[Bq * Hq * Nq * Dq];
__device__ float g_ei[Bq * Hq * Nq];
__device__ float g_ej[Bq * Hq * Nq];
__device__ int   g_sink;

// ---- packed f32x2 helpers (k_gemm) ----------------------------------------
__device__ __forceinline__ unsigned long long pk2(float lo, float hi) {
    unsigned long long r;
    asm("mov.b64 %0, {%1,%2};" : "=l"(r) : "f"(lo), "f"(hi));
    return r;
}
__device__ __forceinline__ void fma2(unsigned long long& d,
                                     unsigned long long a,
                                     unsigned long long b) {
    asm("fma.rn.f32x2 %0, %1, %2, %0;" : "+l"(d) : "l"(a), "l"(b));
}
__device__ __forceinline__ float2 upk(unsigned long long v) {
    float2 f;
    asm("mov.b64 {%0,%1}, %2;" : "=f"(f.x), "=f"(f.y) : "l"(v));
    return f;
}

// ---- mma.sync helpers (sm_80+ features, legal on sm_103) ------------------
__device__ __forceinline__ uint32_t s2u(const void* p) {
    uint32_t a;
    asm("{ .reg .u64 t; cvta.to.shared.u64 t, %1; cvt.u32.u64 %0, t; }"
        : "=r"(a) : "l"(p));
    return a;
}
__device__ __forceinline__ void ldsm4(uint32_t* r, uint32_t a) {
    asm volatile("ldmatrix.sync.aligned.m8n8.x4.shared.b16 {%0,%1,%2,%3},[%4];"
                 : "=r"(r[0]), "=r"(r[1]), "=r"(r[2]), "=r"(r[3]) : "r"(a));
}
__device__ __forceinline__ void ldsm4t(uint32_t* r, uint32_t a) {
    asm volatile(
        "ldmatrix.sync.aligned.m8n8.x4.trans.shared.b16 {%0,%1,%2,%3},[%4];"
        : "=r"(r[0]), "=r"(r[1]), "=r"(r[2]), "=r"(r[3]) : "r"(a));
}
__device__ __forceinline__ void ldsm2t(uint32_t* r, uint32_t a) {
    asm volatile(
        "ldmatrix.sync.aligned.m8n8.x2.trans.shared.b16 {%0,%1},[%2];"
        : "=r"(r[0]), "=r"(r[1]) : "r"(a));
}
__device__ __forceinline__ void mmab(float* c, const uint32_t* a,
                                     const uint32_t* b) {
    asm volatile(
        "mma.sync.aligned.m16n8k16.row.col.f32.bf16.bf16.f32 "
        "{%0,%1,%2,%3},{%4,%5,%6,%7},{%8,%9},{%0,%1,%2,%3};"
        : "+f"(c[0]), "+f"(c[1]), "+f"(c[2]), "+f"(c[3])
        : "r"(a[0]), "r"(a[1]), "r"(a[2]), "r"(a[3]), "r"(b[0]), "r"(b[1]));
}
__device__ __forceinline__ uint32_t pbf(float x, float y) {
    __nv_bfloat162 t = __floats2bfloat162_rn(x, y);
    return *(uint32_t*)&t;
}

// ---------------------------------------------------------------------------
// Kernel 1: h = x @ W -> g_h[b][head][n][d]
// ---------------------------------------------------------------------------
__global__ __launch_bounds__(256) void k_gemm(const float* __restrict__ x,
                                              const float* __restrict__ W) {
    __shared__ float Ws[32 * 256];
    __shared__ float xs[32 * 33];

    const int tid  = threadIdx.x;
    const int row0 = blockIdx.x * 32;
    const int ty   = tid >> 4;
    const int tx   = tid & 15;

    unsigned long long acc2[2][8];
#pragma unroll
    for (int r = 0; r < 2; r++)
#pragma unroll
        for (int c = 0; c < 8; c++) acc2[r][c] = 0ull;

    for (int kc = 0; kc < FIN; kc += 32) {
        __syncthreads();
        const float4* W4 = (const float4*)(W + kc * 256);
#pragma unroll
        for (int t = 0; t < 8; t++) {
            int idx = tid + 256 * t;
            ((float4*)Ws)[idx] = W4[idx];
        }
        {
            int r  = tid >> 3;
            int kq = tid & 7;
            float4 v = *(const float4*)(x + (size_t)(row0 + r) * FIN + kc + kq * 4);
            float* dst = &xs[r * 33 + kq * 4];
            dst[0] = v.x; dst[1] = v.y; dst[2] = v.z; dst[3] = v.w;
        }
        __syncthreads();
#pragma unroll
        for (int k = 0; k < 32; k++) {
            float x0 = xs[(ty * 2 + 0) * 33 + k];
            float x1 = xs[(ty * 2 + 1) * 33 + k];
            unsigned long long xp0 = pk2(x0, x0);
            unsigned long long xp1 = pk2(x1, x1);
#pragma unroll
            for (int c = 0; c < 8; c++) {
                unsigned long long wv =
                    *(const unsigned long long*)&Ws[k * 256 + tx * 2 + c * 32];
                fma2(acc2[0][c], xp0, wv);
                fma2(acc2[1][c], xp1, wv);
            }
        }
    }
#pragma unroll
    for (int r = 0; r < 2; r++) {
        int g = row0 + ty * 2 + r;
        int b = g / Nq;
        int n = g % Nq;
#pragma unroll
        for (int c = 0; c < 8; c++) {
            int o    = tx * 2 + c * 32;
            int head = o >> 6;
            int d    = o & 63;
            float2 v = upk(acc2[r][c]);
            *(float2*)&g_h[(((size_t)b * Hq + head) * Nq + n) * Dq + d] = v;
        }
    }
}

// ---------------------------------------------------------------------------
// Kernel 2: ei/ej per (b,head,n). One warp per row.
// ---------------------------------------------------------------------------
__global__ __launch_bounds__(256) void k_ev(const float* __restrict__ a) {
    int task = blockIdx.x * 8 + (threadIdx.x >> 5);
    int lane = threadIdx.x & 31;
    const float* hr = g_h + (size_t)task * Dq;
    float v0 = hr[lane], v1 = hr[lane + 32];
    float e1 = v0 * a[lane]      + v1 * a[lane + 32];
    float e2 = v0 * a[64 + lane] + v1 * a[96 + lane];
#pragma unroll
    for (int off = 16; off > 0; off >>= 1) {
        e1 += __shfl_down_sync(0xffffffffu, e1, off);
        e2 += __shfl_down_sync(0xffffffffu, e2, off);
    }
    if (lane == 0) {
        g_ei[task] = e1;
        g_ej[task] = e2;
    }
}

// dummy: keeps ncu's fixed capture slot on k_attn (4th launch)
__global__ void k_dummy() {
    if (threadIdx.x == 0 && blockIdx.x == 0) g_sink = 1;
}

// ---------------------------------------------------------------------------
// Kernel 3: GAT attention via mma.sync bf16.
// num_i = e^{ei}(A.U)_i + e^{0.2ei}(B.L)_i ; den as extra column (V==1).
// A=adj&(ei+ej>=0), B=adj&~, exact {0,1} bf16. U/L bf16 hi+lo split.
// CTA = (b, head, 128-i-tile) = 256 CTAs, 8 warps, each warp 16 rows x 72 cols.
// j processed in 32 chunks of 64 (K=64 per chunk, 4 k16 steps).
// ---------------------------------------------------------------------------
#define PITA 144    // A/B mask tile row pitch bytes (64 bf16 + 8 pad)
#define PITU 176    // U/L tile row pitch bytes (72 bf16 data + 16 pad)
#define OFF_B   18432
#define OFF_UH  36864
#define OFF_UL  48128
#define OFF_LH  59392
#define OFF_LL  70656
#define OFF_X1  81920
#define OFF_X2  90112
#define OFF_EJ  98304
#define SMEM_AT 106496

__global__ __launch_bounds__(256, 2) void k_attn(const int* __restrict__ adj) {
    extern __shared__ char dyn[];
    __shared__ float ei_s[128];

    char*  Asm   = dyn;
    char*  Bsm   = dyn + OFF_B;
    char*  Uhm   = dyn + OFF_UH;
    char*  Ulm   = dyn + OFF_UL;
    char*  Lhm   = dyn + OFF_LH;
    char*  Llm   = dyn + OFF_LL;
    float* exj1f = (float*)(dyn + OFF_X1);
    float* exj2f = (float*)(dyn + OFF_X2);
    float* ejf   = (float*)(dyn + OFF_EJ);

    const int tid  = threadIdx.x;
    const int wid  = tid >> 5;
    const int lane = tid & 31;
    const int it   = blockIdx.x & 15;
    const int head = (blockIdx.x >> 4) & 3;
    const int b    = blockIdx.x >> 6;
    const int i0   = it * 128;
    const int bh   = b * Hq + head;
    const int m0   = wid * 16;

    const float* Vg = g_h + (size_t)bh * Nq * Dq;

    // hoist: ej, exp(ej), exp(.2 ej) for all 2048 j; ei for this i-tile
#pragma unroll
    for (int t = 0; t < 8; t++) {
        int j = tid + 256 * t;
        float e = g_ej[bh * Nq + j];
        ejf[j]   = e;
        exj1f[j] = __expf(e);
        exj2f[j] = __expf(0.2f * e);
    }
    if (tid < 128) ei_s[tid] = g_ei[bh * Nq + i0 + tid];
    __syncthreads();

    // smem base addrs (32-bit shared space) for ldmatrix
    const uint32_t AsU = s2u(Asm), BsU = s2u(Bsm);
    const uint32_t UhU = s2u(Uhm), UlU = s2u(Ulm);
    const uint32_t LhU = s2u(Lhm), LlU = s2u(Llm);
    const uint32_t aLane = AsU + (uint32_t)(m0 + (lane & 15)) * PITA +
                           (uint32_t)(lane >> 4) * 16;
    const uint32_t bLaneA = BsU + (uint32_t)(m0 + (lane & 15)) * PITA +
                            (uint32_t)(lane >> 4) * 16;
    const uint32_t uLane = (uint32_t)(lane & 15) * PITU +
                           (uint32_t)(lane >> 4) * 16;

    // build-phase thread mapping
    const int   mi   = tid >> 1;              // mask row 0..127
    const int   jh   = (tid & 1) * 32;        // mask j-half
    const float eIv  = ei_s[mi];
    const int*  ar0  = adj + ((size_t)b * Nq + i0 + mi) * Nq;
    const int   uj   = tid >> 2;              // U row 0..63
    const int   dq   = (tid & 3) * 16;        // d quarter

    float C1[9][4], C2[9][4];
#pragma unroll
    for (int t = 0; t < 9; t++)
#pragma unroll
        for (int q = 0; q < 4; q++) { C1[t][q] = 0.f; C2[t][q] = 0.f; }

    for (int ch = 0; ch < 32; ch++) {
        const int j0 = ch * 64;
        __syncthreads();   // previous chunk's ldmatrix done

        // ---- masks A,B: thread owns row mi, 32 j ----
        {
            const int4* ap = (const int4*)(ar0 + j0 + jh);
#pragma unroll
            for (int q = 0; q < 8; q++) {
                int4 m = ap[q];
                int j  = jh + 4 * q;
                float s0 = eIv + ejf[j0 + j + 0];
                float s1 = eIv + ejf[j0 + j + 1];
                float s2 = eIv + ejf[j0 + j + 2];
                float s3 = eIv + ejf[j0 + j + 3];
                uint32_t a0 = (m.x && s0 >= 0.f) ? 0x3F80u : 0u;
                uint32_t a1 = (m.y && s1 >= 0.f) ? 0x3F80u : 0u;
                uint32_t a2 = (m.z && s2 >= 0.f) ? 0x3F80u : 0u;
                uint32_t a3 = (m.w && s3 >= 0.f) ? 0x3F80u : 0u;
                uint32_t b0 = (m.x && s0 < 0.f) ? 0x3F80u : 0u;
                uint32_t b1 = (m.y && s1 < 0.f) ? 0x3F80u : 0u;
                uint32_t b2 = (m.z && s2 < 0.f) ? 0x3F80u : 0u;
                uint32_t b3 = (m.w && s3 < 0.f) ? 0x3F80u : 0u;
                uint2 pa = make_uint2(a0 | (a1 << 16), a2 | (a3 << 16));
                uint2 pb = make_uint2(b0 | (b1 << 16), b2 | (b3 << 16));
                *(uint2*)(Asm + mi * PITA + j * 2) = pa;
                *(uint2*)(Bsm + mi * PITA + j * 2) = pb;
            }
        }

        // ---- U/L tiles: thread owns row uj, 16 d-cols ----
        {
            const float* vr = Vg + (size_t)(j0 + uj) * Dq + dq;
            float x1 = exj1f[j0 + uj];
            float x2 = exj2f[j0 + uj];
            float v[16];
#pragma unroll
            for (int g = 0; g < 4; g++) {
                float4 f = *(const float4*)(vr + 4 * g);
                v[4 * g] = f.x; v[4 * g + 1] = f.y;
                v[4 * g + 2] = f.z; v[4 * g + 3] = f.w;
            }
            uint32_t uh[8], ul[8], lh[8], ll[8];
#pragma unroll
            for (int g = 0; g < 8; g++) {
                float p0 = v[2 * g] * x1, p1 = v[2 * g + 1] * x1;
                float q0 = v[2 * g] * x2, q1 = v[2 * g + 1] * x2;
                float ph0 = __bfloat162float(__float2bfloat16(p0));
                float ph1 = __bfloat162float(__float2bfloat16(p1));
                float qh0 = __bfloat162float(__float2bfloat16(q0));
                float qh1 = __bfloat162float(__float2bfloat16(q1));
                uh[g] = pbf(ph0, ph1);
                ul[g] = pbf(p0 - ph0, p1 - ph1);
                lh[g] = pbf(qh0, qh1);
                ll[g] = pbf(q0 - qh0, q1 - qh1);
            }
            char* rowo = (char*)(size_t)(uj * PITU + dq * 2);
            *(uint4*)(Uhm + (size_t)rowo)      = *(uint4*)&uh[0];
            *(uint4*)(Uhm + (size_t)rowo + 16) = *(uint4*)&uh[4];
            *(uint4*)(Ulm + (size_t)rowo)      = *(uint4*)&ul[0];
            *(uint4*)(Ulm + (size_t)rowo + 16) = *(uint4*)&ul[4];
            *(uint4*)(Lhm + (size_t)rowo)      = *(uint4*)&lh[0];
            *(uint4*)(Lhm + (size_t)rowo + 16) = *(uint4*)&lh[4];
            *(uint4*)(Llm + (size_t)rowo)      = *(uint4*)&ll[0];
            *(uint4*)(Llm + (size_t)rowo + 16) = *(uint4*)&ll[4];
            if ((tid & 3) == 3) {   // den column 64 (+ zeros 65-71)
                float h1 = __bfloat162float(__float2bfloat16(x1));
                float h2 = __bfloat162float(__float2bfloat16(x2));
                size_t doff = (size_t)(uj * PITU + 128);
                *(uint4*)(Uhm + doff) = make_uint4(pbf(h1, 0.f), 0, 0, 0);
                *(uint4*)(Ulm + doff) = make_uint4(pbf(x1 - h1, 0.f), 0, 0, 0);
                *(uint4*)(Lhm + doff) = make_uint4(pbf(h2, 0.f), 0, 0, 0);
                *(uint4*)(Llm + doff) = make_uint4(pbf(x2 - h2, 0.f), 0, 0, 0);
            }
        }
        __syncthreads();

        // ---- compute: 4 k16 steps ----
#pragma unroll
        for (int ks = 0; ks < 4; ks++) {
            uint32_t a1[4], a2[4];
            ldsm4(a1, aLane + ks * 32);
            ldsm4(a2, bLaneA + ks * 32);
            const uint32_t ub = uLane + ks * 16 * PITU;
#pragma unroll
            for (int ng = 0; ng < 4; ng++) {
                uint32_t f0[4], f1[4];
                ldsm4t(f0, UhU + ub + ng * 32);
                ldsm4t(f1, UlU + ub + ng * 32);
                mmab(C1[2 * ng],     a1, f0);
                mmab(C1[2 * ng + 1], a1, f0 + 2);
                mmab(C1[2 * ng],     a1, f1);
                mmab(C1[2 * ng + 1], a1, f1 + 2);
                ldsm4t(f0, LhU + ub + ng * 32);
                ldsm4t(f1, LlU + ub + ng * 32);
                mmab(C2[2 * ng],     a2, f0);
                mmab(C2[2 * ng + 1], a2, f0 + 2);
                mmab(C2[2 * ng],     a2, f1);
                mmab(C2[2 * ng + 1], a2, f1 + 2);
            }
            {   // den n-tile (cols 64-71)
                uint32_t t0[2];
                ldsm2t(t0, UhU + ub + 128); mmab(C1[8], a1, t0);
                ldsm2t(t0, UlU + ub + 128); mmab(C1[8], a1, t0);
                ldsm2t(t0, LhU + ub + 128); mmab(C2[8], a2, t0);
                ldsm2t(t0, LlU + ub + 128); mmab(C2[8], a2, t0);
            }
        }
    }

    // ---- readout: rows m0+r0, m0+r0+8; cols (lane&3)*2 + 8*tile ----
    const int r0   = lane >> 2;
    const int c0   = (lane & 3) * 2;
    const int row0 = m0 + r0, row1 = row0 + 8;
    const int src  = lane & 28;
    float d1a = __shfl_sync(0xffffffffu, C1[8][0], src);
    float d2a = __shfl_sync(0xffffffffu, C2[8][0], src);
    float d1b = __shfl_sync(0xffffffffu, C1[8][2], src);
    float d2b = __shfl_sync(0xffffffffu, C2[8][2], src);
    float sA0 = __expf(ei_s[row0]), sB0 = __expf(0.2f * ei_s[row0]);
    float sA1 = __expf(ei_s[row1]), sB1 = __expf(0.2f * ei_s[row1]);
    float inv0 = 1.f / (sA0 * d1a + sB0 * d2a);
    float inv1 = 1.f / (sA1 * d1b + sB1 * d2b);

    float* og0 = g_o + ((size_t)bh * Nq + i0 + row0) * Dq;
    float* og1 = g_o + ((size_t)bh * Nq + i0 + row1) * Dq;
#pragma unroll
    for (int t = 0; t < 8; t++) {
        float2 o0, o1;
        o0.x = (sA0 * C1[t][0] + sB0 * C2[t][0]) * inv0;
        o0.y = (sA0 * C1[t][1] + sB0 * C2[t][1]) * inv0;
        o1.x = (sA1 * C1[t][2] + sB1 * C2[t][2]) * inv1;
        o1.y = (sA1 * C1[t][3] + sB1 * C2[t][3]) * inv1;
        *(float2*)&og0[8 * t + c0] = o0;
        *(float2*)&og1[8 * t + c0] = o1;
    }
}

// ---------------------------------------------------------------------------
// Kernel 5: out[b][n][d] = mean over heads of g_o
// ---------------------------------------------------------------------------
__global__ __launch_bounds__(256) void k_mean(float* __restrict__ out) {
    int idx = blockIdx.x * 256 + threadIdx.x;
    if (idx >= Bq * Nq * Dq) return;
    int d = idx & 63;
    int n = (idx >> 6) & (Nq - 1);
    int b = idx >> 17;
    float s = 0.f;
#pragma unroll
    for (int h = 0; h < Hq; h++)
        s += g_o[(((size_t)b * Hq + h) * Nq + n) * Dq + d];
    out[idx] = 0.25f * s;
}

// ---------------------------------------------------------------------------
extern "C" void kernel_launch(void* const* d_in, const int* in_sizes, int n_in,
                              void* d_out, int out_size) {
    const float* x   = (const float*)d_in[0];
    const int*   adj = (const int*)  d_in[1];
    const float* W   = (const float*)d_in[2];
    const float* a   = (const float*)d_in[3];
    float*       out = (float*)d_out;

    cudaFuncSetAttribute(k_attn, cudaFuncAttributeMaxDynamicSharedMemorySize,
                         SMEM_AT);

    k_gemm <<<(Bq * Nq) / 32, 256>>>(x, W);
    k_ev   <<<(Bq * Hq * Nq) / 8, 256>>>(a);
    k_dummy<<<1, 32>>>();
    k_attn <<<Bq * Hq * (Nq / 128), 256, SMEM_AT>>>(adj);
    k_mean <<<(Bq * Nq * Dq + 255) / 256, 256>>>(out);
}